// round 2
// baseline (speedup 1.0000x reference)
#include <cuda_runtime.h>
#include <math.h>

#define H    2048
#define II   4096
#define E    8
#define NTOK 2048
#define GU   (2*II)   // 8192

#define TM 64
#define TN 64
#define TK 16

// ---------------- scratch (static device globals; no runtime alloc) ----------
__device__ int   g_cnt[E];                       // tokens routed per expert
__device__ int   g_tok[E * NTOK];                // token index per (expert, slot)
__device__ int   g_slot[NTOK * 2];               // per token: global slot (e*NTOK+s) of its 2 picks
__device__ float g_w[NTOK * 2];                  // per token: renormalized top-2 weights
__device__ float g_mid[(size_t)(E + 1) * NTOK * II];   // silu(gate)*up activations; seg 8 = base
__device__ float g_pout[(size_t)E * NTOK * H];         // per-pair down-proj outputs

// ---------------- reset per-launch state -------------------------------------
__global__ void k_zero() {
    if (threadIdx.x < E) g_cnt[threadIdx.x] = 0;
}

// ---------------- router: logits -> softmax top-2 -> renorm -> dispatch ------
__global__ void k_router(const float* __restrict__ x, const float* __restrict__ gate_w) {
    int n = blockIdx.x;
    __shared__ float red[256][E];
    const float* xr = x + (size_t)n * H;
    float acc[E];
#pragma unroll
    for (int e = 0; e < E; e++) acc[e] = 0.f;
    for (int h = threadIdx.x; h < H; h += 256) {
        float xv = xr[h];
        const float* gw = gate_w + (size_t)h * E;
#pragma unroll
        for (int e = 0; e < E; e++) acc[e] += xv * gw[e];
    }
#pragma unroll
    for (int e = 0; e < E; e++) red[threadIdx.x][e] = acc[e];
    __syncthreads();
    for (int s = 128; s > 0; s >>= 1) {
        if (threadIdx.x < s) {
#pragma unroll
            for (int e = 0; e < E; e++) red[threadIdx.x][e] += red[threadIdx.x + s][e];
        }
        __syncthreads();
    }
    if (threadIdx.x == 0) {
        float l[E];
#pragma unroll
        for (int e = 0; e < E; e++) l[e] = red[0][e];
        // top-2 of logits (== top-2 of softmax probs); strict > keeps lowest index on ties
        int i0 = 0;
        for (int e = 1; e < E; e++) if (l[e] > l[i0]) i0 = e;
        int i1 = -1;
        for (int e = 0; e < E; e++) {
            if (e == i0) continue;
            if (i1 < 0 || l[e] > l[i1]) i1 = e;
        }
        // renormalized weights over the top-2 = 2-way softmax of their logits
        float m  = fmaxf(l[i0], l[i1]);
        float e0 = expf(l[i0] - m), e1 = expf(l[i1] - m);
        float inv = 1.f / (e0 + e1);
        int s0 = atomicAdd(&g_cnt[i0], 1);
        int s1 = atomicAdd(&g_cnt[i1], 1);
        g_tok[i0 * NTOK + s0] = n;
        g_tok[i1 * NTOK + s1] = n;
        g_slot[n * 2 + 0] = i0 * NTOK + s0;
        g_slot[n * 2 + 1] = i1 * NTOK + s1;
        g_w[n * 2 + 0] = e0 * inv;
        g_w[n * 2 + 1] = e1 * inv;
    }
}

// ---------------- grouped GEMM: gate_up + SiLU*mul ---------------------------
// seg 0..7 = experts (gathered rows), seg 8 = base (all tokens)
__global__ void __launch_bounds__(256) k_gateup(const float* __restrict__ x,
                                                const float* __restrict__ base_gu,
                                                const float* __restrict__ exp_gu) {
    int seg = blockIdx.z;
    int m0 = blockIdx.y * TM;
    int n0 = blockIdx.x * TN;     // column tile in [0, II)
    int M;
    const int* tokp = nullptr;
    const float* B;
    if (seg < E) {
        M = g_cnt[seg];
        tokp = g_tok + seg * NTOK;
        B = exp_gu + (size_t)seg * H * GU;
    } else {
        M = NTOK;
        B = base_gu;
    }
    if (m0 >= M) return;

    __shared__ float As[TK][TM];
    __shared__ float Bg[TK][TN];
    __shared__ float Bu[TK][TN];

    int tid = threadIdx.x;
    int tm = tid >> 4, tn = tid & 15;

    float accg[4][4] = {}, accu[4][4] = {};

    int arow = tid >> 2;                 // 0..63
    int acol4 = (tid & 3) * 4;           // 0,4,8,12
    int grow = m0 + arow;
    if (grow >= M) grow = M - 1;         // safe clamp (M>=1 here)
    int gtokn = (seg < E) ? tokp[grow] : grow;
    const float* arp = x + (size_t)gtokn * H;

    int brow = tid >> 4;                 // 0..15
    int bcol4 = (tid & 15) * 4;          // 0..60

    for (int k0 = 0; k0 < H; k0 += TK) {
        float4 av  = *(const float4*)(arp + k0 + acol4);
        const float* brp = B + (size_t)(k0 + brow) * GU;
        float4 bgv = *(const float4*)(brp + n0 + bcol4);
        float4 buv = *(const float4*)(brp + II + n0 + bcol4);
        As[acol4 + 0][arow] = av.x;
        As[acol4 + 1][arow] = av.y;
        As[acol4 + 2][arow] = av.z;
        As[acol4 + 3][arow] = av.w;
        *(float4*)&Bg[brow][bcol4] = bgv;
        *(float4*)&Bu[brow][bcol4] = buv;
        __syncthreads();
#pragma unroll
        for (int kk = 0; kk < TK; kk++) {
            float a[4], bg[4], bu[4];
            *(float4*)a  = *(const float4*)&As[kk][tm * 4];
            *(float4*)bg = *(const float4*)&Bg[kk][tn * 4];
            *(float4*)bu = *(const float4*)&Bu[kk][tn * 4];
#pragma unroll
            for (int i2 = 0; i2 < 4; i2++) {
#pragma unroll
                for (int j = 0; j < 4; j++) {
                    accg[i2][j] += a[i2] * bg[j];
                    accu[i2][j] += a[i2] * bu[j];
                }
            }
        }
        __syncthreads();
    }

    float* midseg = g_mid + (size_t)seg * NTOK * II;
#pragma unroll
    for (int i2 = 0; i2 < 4; i2++) {
        int m = m0 + tm * 4 + i2;
        if (m >= M) continue;
        float* outp = midseg + (size_t)m * II + n0 + tn * 4;
#pragma unroll
        for (int j = 0; j < 4; j++) {
            float gv = accg[i2][j];
            float s = gv / (1.f + expf(-gv));   // silu
            outp[j] = s * accu[i2][j];
        }
    }
}

// ---------------- grouped GEMM: down projection ------------------------------
__global__ void __launch_bounds__(256) k_down(const float* __restrict__ base_down,
                                              const float* __restrict__ exp_down,
                                              float* __restrict__ out) {
    int seg = blockIdx.z;
    int m0 = blockIdx.y * TM;
    int n0 = blockIdx.x * TN;    // H columns
    int M;
    const float* B;
    if (seg < E) { M = g_cnt[seg]; B = exp_down + (size_t)seg * II * H; }
    else         { M = NTOK;       B = base_down; }
    if (m0 >= M) return;
    const float* Abase = g_mid + (size_t)seg * NTOK * II;

    __shared__ float As[TK][TM];
    __shared__ float Bs[TK][TN];

    int tid = threadIdx.x;
    int tm = tid >> 4, tn = tid & 15;
    float acc[4][4] = {};

    int arow = tid >> 2;
    int acol4 = (tid & 3) * 4;
    int grow = m0 + arow;
    if (grow >= M) grow = M - 1;
    const float* arp = Abase + (size_t)grow * II;

    int brow = tid >> 4;
    int bcol4 = (tid & 15) * 4;

    for (int k0 = 0; k0 < II; k0 += TK) {
        float4 av = *(const float4*)(arp + k0 + acol4);
        float4 bv = *(const float4*)(B + (size_t)(k0 + brow) * H + n0 + bcol4);
        As[acol4 + 0][arow] = av.x;
        As[acol4 + 1][arow] = av.y;
        As[acol4 + 2][arow] = av.z;
        As[acol4 + 3][arow] = av.w;
        *(float4*)&Bs[brow][bcol4] = bv;
        __syncthreads();
#pragma unroll
        for (int kk = 0; kk < TK; kk++) {
            float a[4], b[4];
            *(float4*)a = *(const float4*)&As[kk][tm * 4];
            *(float4*)b = *(const float4*)&Bs[kk][tn * 4];
#pragma unroll
            for (int i2 = 0; i2 < 4; i2++) {
#pragma unroll
                for (int j = 0; j < 4; j++) acc[i2][j] += a[i2] * b[j];
            }
        }
        __syncthreads();
    }

    float* C = (seg < E) ? (g_pout + (size_t)seg * NTOK * H) : out;
#pragma unroll
    for (int i2 = 0; i2 < 4; i2++) {
        int m = m0 + tm * 4 + i2;
        if (m >= M) continue;
        float* cp = C + (size_t)m * H + n0 + tn * 4;
#pragma unroll
        for (int j = 0; j < 4; j++) cp[j] = acc[i2][j];
    }
}

// ---------------- deterministic combine: out = base + w0*y0 + w1*y1 ----------
__global__ void k_combine(float* __restrict__ out) {
    int n = blockIdx.y;
    int h4 = (blockIdx.x * blockDim.x + threadIdx.x) * 4;
    int s0 = g_slot[n * 2 + 0], s1 = g_slot[n * 2 + 1];
    float w0 = g_w[n * 2 + 0],  w1 = g_w[n * 2 + 1];
    float* op = out + (size_t)n * H + h4;
    float4 o  = *(float4*)op;
    float4 p0 = *(const float4*)(g_pout + (size_t)s0 * H + h4);
    float4 p1 = *(const float4*)(g_pout + (size_t)s1 * H + h4);
    o.x += w0 * p0.x + w1 * p1.x;
    o.y += w0 * p0.y + w1 * p1.y;
    o.z += w0 * p0.z + w1 * p1.z;
    o.w += w0 * p0.w + w1 * p1.w;
    *(float4*)op = o;
}

// ---------------- launch ------------------------------------------------------
extern "C" void kernel_launch(void* const* d_in, const int* in_sizes, int n_in,
                              void* d_out, int out_size) {
    const float* x         = (const float*)d_in[0];
    const float* gate_w    = (const float*)d_in[1];
    const float* base_gu   = (const float*)d_in[2];
    const float* base_down = (const float*)d_in[3];
    const float* exp_gu    = (const float*)d_in[4];
    const float* exp_down  = (const float*)d_in[5];
    float* out = (float*)d_out;

    k_zero<<<1, 32>>>();
    k_router<<<NTOK, 256>>>(x, gate_w);
    k_gateup<<<dim3(II / TN, NTOK / TM, E + 1), 256>>>(x, base_gu, exp_gu);
    k_down<<<dim3(H / TN, NTOK / TM, E + 1), 256>>>(base_down, exp_down, out);
    k_combine<<<dim3(H / (4 * 128), NTOK), 128>>>(out);
}

// round 4
// speedup vs baseline: 2.7586x; 2.7586x over previous
#include <cuda_runtime.h>
#include <math.h>
#include <stdint.h>

#define H    2048
#define II   4096
#define E    8
#define NTOK 2048
#define GU   (2*II)

#define BM 128
#define BK 16
#define NS 4            // pipeline stages

#define A_STRIDE 20     // floats per A row in smem (16 + 4 pad; bank-conflict-free)
#define B_STRIDE 136    // floats per B row in smem (128 + 8 pad; bank-conflict-free)
#define A_SZ (BM * A_STRIDE)        // 2560 floats / stage
#define B_SZ (BK * B_STRIDE)        // 2176 floats / stage
#define SMEM_BYTES ((NS * A_SZ + NS * B_SZ) * 4)   // 75776

// ---------------- scratch ------------------------------------------------------
__device__ int   g_cnt[E];
__device__ int   g_tok[E * NTOK];
__device__ int   g_slot[NTOK * 2];
__device__ float g_w[NTOK * 2];
__device__ float g_mid[(size_t)(E + 1) * NTOK * II];
__device__ float g_pout[(size_t)E * NTOK * H];

// ---------------- helpers ------------------------------------------------------
__device__ __forceinline__ uint32_t smem_u32(const void* p) {
    uint32_t a;
    asm("{ .reg .u64 t; cvta.to.shared.u64 t, %1; cvt.u32.u64 %0, t; }" : "=r"(a) : "l"(p));
    return a;
}
__device__ __forceinline__ uint32_t f2tf(float f) {
    uint32_t u;
    asm("cvt.rna.tf32.f32 %0, %1;" : "=r"(u) : "f"(f));
    return u;
}
__device__ __forceinline__ void mma8(float* c, const uint32_t* a, const uint32_t* b) {
    asm volatile(
        "mma.sync.aligned.m16n8k8.row.col.f32.tf32.tf32.f32 "
        "{%0,%1,%2,%3}, {%4,%5,%6,%7}, {%8,%9}, {%0,%1,%2,%3};"
        : "+f"(c[0]), "+f"(c[1]), "+f"(c[2]), "+f"(c[3])
        : "r"(a[0]), "r"(a[1]), "r"(a[2]), "r"(a[3]), "r"(b[0]), "r"(b[1]));
}
__device__ __forceinline__ void cpa16(uint32_t dst, const void* src) {
    asm volatile("cp.async.cg.shared.global [%0], [%1], 16;" :: "r"(dst), "l"(src) : "memory");
}
#define CP_COMMIT() asm volatile("cp.async.commit_group;" ::: "memory")
#define CP_WAIT2()  asm volatile("cp.async.wait_group 2;" ::: "memory")
#define CP_WAIT0()  asm volatile("cp.async.wait_group 0;" ::: "memory")

__device__ __forceinline__ float silu(float g) { return g / (1.f + __expf(-g)); }

// ---------------- small kernels --------------------------------------------------
__global__ void k_zero() { if (threadIdx.x < E) g_cnt[threadIdx.x] = 0; }

__global__ void k_router(const float* __restrict__ x, const float* __restrict__ gate_w) {
    int n = blockIdx.x;
    __shared__ float red[256][E];
    const float* xr = x + (size_t)n * H;
    float acc[E];
#pragma unroll
    for (int e = 0; e < E; e++) acc[e] = 0.f;
    for (int h = threadIdx.x; h < H; h += 256) {
        float xv = xr[h];
        const float* gw = gate_w + (size_t)h * E;
#pragma unroll
        for (int e = 0; e < E; e++) acc[e] += xv * gw[e];
    }
#pragma unroll
    for (int e = 0; e < E; e++) red[threadIdx.x][e] = acc[e];
    __syncthreads();
    for (int s = 128; s > 0; s >>= 1) {
        if (threadIdx.x < s) {
#pragma unroll
            for (int e = 0; e < E; e++) red[threadIdx.x][e] += red[threadIdx.x + s][e];
        }
        __syncthreads();
    }
    if (threadIdx.x == 0) {
        float l[E];
#pragma unroll
        for (int e = 0; e < E; e++) l[e] = red[0][e];
        int i0 = 0;
        for (int e = 1; e < E; e++) if (l[e] > l[i0]) i0 = e;
        int i1 = -1;
        for (int e = 0; e < E; e++) {
            if (e == i0) continue;
            if (i1 < 0 || l[e] > l[i1]) i1 = e;
        }
        float m  = fmaxf(l[i0], l[i1]);
        float e0 = expf(l[i0] - m), e1 = expf(l[i1] - m);
        float inv = 1.f / (e0 + e1);
        int s0 = atomicAdd(&g_cnt[i0], 1);
        int s1 = atomicAdd(&g_cnt[i1], 1);
        g_tok[i0 * NTOK + s0] = n;
        g_tok[i1 * NTOK + s1] = n;
        g_slot[n * 2 + 0] = i0 * NTOK + s0;
        g_slot[n * 2 + 1] = i1 * NTOK + s1;
        g_w[n * 2 + 0] = e0 * inv;
        g_w[n * 2 + 1] = e1 * inv;
    }
}

__global__ void k_combine(float* __restrict__ out) {
    int n = blockIdx.y;
    int h4 = (blockIdx.x * blockDim.x + threadIdx.x) * 4;
    int s0 = g_slot[n * 2 + 0], s1 = g_slot[n * 2 + 1];
    float w0 = g_w[n * 2 + 0],  w1 = g_w[n * 2 + 1];
    float* op = out + (size_t)n * H + h4;
    float4 o  = *(float4*)op;
    float4 p0 = *(const float4*)(g_pout + (size_t)s0 * H + h4);
    float4 p1 = *(const float4*)(g_pout + (size_t)s1 * H + h4);
    o.x += w0 * p0.x + w1 * p1.x;
    o.y += w0 * p0.y + w1 * p1.y;
    o.z += w0 * p0.z + w1 * p1.z;
    o.w += w0 * p0.w + w1 * p1.w;
    *(float4*)op = o;
}

// =================================================================================
// GEMM1: gate_up with fused SiLU*mul.  Block: 128 rows x (64 gate + 64 up cols).
// grid (II/64, NTOK/BM, E+1), 256 threads.
// =================================================================================
__global__ void __launch_bounds__(256) k_gateup_tc(
    const float* __restrict__ x, const float* __restrict__ base_gu,
    const float* __restrict__ exp_gu)
{
    int seg = blockIdx.z;
    int m0 = blockIdx.y * BM;
    int n0g = blockIdx.x * 64;
    int M; const int* tokp = nullptr; const float* Bw;
    if (seg < E) { M = g_cnt[seg]; tokp = g_tok + seg * NTOK; Bw = exp_gu + (size_t)seg * H * GU; }
    else         { M = NTOK;       Bw = base_gu; }
    if (m0 >= M) return;

    extern __shared__ float sm[];
    float* sA = sm;
    float* sB = sm + NS * A_SZ;
    uint32_t smb = smem_u32(sm);
    uint32_t smbB = smb + NS * A_SZ * 4;

    int tid = threadIdx.x, lane = tid & 31, wid = tid >> 5;
    int wm = wid & 3, wn = wid >> 2;
    int g4 = lane >> 2, l4 = lane & 3;

    // fill assignments
    int fr = tid >> 1, fq = tid & 1;                 // A: row fr, two float4s
    int amr = min(m0 + fr, M - 1);
    const float* arp = x + (size_t)((seg < E) ? tokp[amr] : amr) * H;
    uint32_t adst0 = smb + (fr * A_STRIDE) * 4 + fq * 16;
    int bk = tid >> 4, bh = tid & 15;                // B: row bk, float4s bh & bh+16
    uint32_t bdst0 = smbB + (bk * B_STRIDE) * 4 + bh * 16;

    float acc[2][8][4];
#pragma unroll
    for (int a = 0; a < 2; a++)
#pragma unroll
        for (int b = 0; b < 8; b++)
#pragma unroll
            for (int c = 0; c < 4; c++) acc[a][b][c] = 0.f;

    const int NCH = H / BK;   // 128

#define FILL_GU(s, c) do {                                                       \
    int k0 = (c) * BK;                                                           \
    uint32_t ad = adst0 + (s) * A_SZ * 4;                                        \
    cpa16(ad,      arp + k0 + fq * 4);                                           \
    cpa16(ad + 32, arp + k0 + fq * 4 + 8);                                       \
    const float* brow = Bw + (size_t)(k0 + bk) * GU + n0g;                       \
    uint32_t bd = bdst0 + (s) * B_SZ * 4;                                        \
    cpa16(bd,       brow + bh * 4);                                              \
    cpa16(bd + 256, brow + II + bh * 4);                                         \
} while (0)

#pragma unroll
    for (int c = 0; c < NS - 1; c++) { FILL_GU(c, c); CP_COMMIT(); }

    for (int c = 0; c < NCH; c++) {
        CP_WAIT2();
        __syncthreads();
        const float* As = sA + (c & 3) * A_SZ;
        const float* Bs = sB + (c & 3) * B_SZ;
#pragma unroll
        for (int ks = 0; ks < 2; ks++) {
            uint32_t af[2][4];
#pragma unroll
            for (int ma = 0; ma < 2; ma++) {
                int row = wm * 32 + ma * 16 + g4;
                int base = row * A_STRIDE + ks * 8 + l4;
                af[ma][0] = f2tf(As[base]);
                af[ma][1] = f2tf(As[base + 8 * A_STRIDE]);
                af[ma][2] = f2tf(As[base + 4]);
                af[ma][3] = f2tf(As[base + 8 * A_STRIDE + 4]);
            }
            uint32_t bf[8][2];
#pragma unroll
            for (int na = 0; na < 8; na++) {
                int col = (na < 4) ? (wn * 32 + na * 8) : (64 + wn * 32 + (na - 4) * 8);
                int bb = (ks * 8 + l4) * B_STRIDE + col + g4;
                bf[na][0] = f2tf(Bs[bb]);
                bf[na][1] = f2tf(Bs[bb + 4 * B_STRIDE]);
            }
#pragma unroll
            for (int ma = 0; ma < 2; ma++)
#pragma unroll
                for (int na = 0; na < 8; na++)
                    mma8(acc[ma][na], af[ma], bf[na]);
        }
        int nf = c + NS - 1;
        if (nf < NCH) FILL_GU(nf & 3, nf);
        CP_COMMIT();
    }
    CP_WAIT0();

    // epilogue: silu(gate)*up
    float* midseg = g_mid + (size_t)seg * NTOK * II;
#pragma unroll
    for (int ma = 0; ma < 2; ma++) {
        int r0 = m0 + wm * 32 + ma * 16 + g4;
#pragma unroll
        for (int na = 0; na < 4; na++) {
            int col = n0g + wn * 32 + na * 8 + l4 * 2;
            float* gacc = acc[ma][na];
            float* uacc = acc[ma][na + 4];
            if (r0 < M) {
                float2 v = { silu(gacc[0]) * uacc[0], silu(gacc[1]) * uacc[1] };
                *(float2*)(midseg + (size_t)r0 * II + col) = v;
            }
            if (r0 + 8 < M) {
                float2 v = { silu(gacc[2]) * uacc[2], silu(gacc[3]) * uacc[3] };
                *(float2*)(midseg + (size_t)(r0 + 8) * II + col) = v;
            }
        }
    }
#undef FILL_GU
}

// =================================================================================
// GEMM2: down projection. Block 128x128. grid (H/128, NTOK/BM, E+1), 256 threads.
// =================================================================================
__global__ void __launch_bounds__(256) k_down_tc(
    const float* __restrict__ base_down, const float* __restrict__ exp_down,
    float* __restrict__ out)
{
    int seg = blockIdx.z;
    int m0 = blockIdx.y * BM;
    int n0 = blockIdx.x * 128;
    int M; const float* Bw;
    if (seg < E) { M = g_cnt[seg]; Bw = exp_down + (size_t)seg * II * H; }
    else         { M = NTOK;       Bw = base_down; }
    if (m0 >= M) return;

    extern __shared__ float sm[];
    float* sA = sm;
    float* sB = sm + NS * A_SZ;
    uint32_t smb = smem_u32(sm);
    uint32_t smbB = smb + NS * A_SZ * 4;

    int tid = threadIdx.x, lane = tid & 31, wid = tid >> 5;
    int wm = wid & 3, wn = wid >> 2;
    int g4 = lane >> 2, l4 = lane & 3;

    int fr = tid >> 1, fq = tid & 1;
    int amr = min(m0 + fr, M - 1);
    const float* arp = g_mid + (size_t)(seg * NTOK + amr) * II;
    uint32_t adst0 = smb + (fr * A_STRIDE) * 4 + fq * 16;
    int bk = tid >> 4, bh = tid & 15;
    uint32_t bdst0 = smbB + (bk * B_STRIDE) * 4 + bh * 16;

    float acc[2][8][4];
#pragma unroll
    for (int a = 0; a < 2; a++)
#pragma unroll
        for (int b = 0; b < 8; b++)
#pragma unroll
            for (int c = 0; c < 4; c++) acc[a][b][c] = 0.f;

    const int NCH = II / BK;  // 256

#define FILL_DN(s, c) do {                                                       \
    int k0 = (c) * BK;                                                           \
    uint32_t ad = adst0 + (s) * A_SZ * 4;                                        \
    cpa16(ad,      arp + k0 + fq * 4);                                           \
    cpa16(ad + 32, arp + k0 + fq * 4 + 8);                                       \
    const float* brow = Bw + (size_t)(k0 + bk) * H + n0;                         \
    uint32_t bd = bdst0 + (s) * B_SZ * 4;                                        \
    cpa16(bd,       brow + bh * 4);                                              \
    cpa16(bd + 256, brow + 64 + bh * 4);                                         \
} while (0)

#pragma unroll
    for (int c = 0; c < NS - 1; c++) { FILL_DN(c, c); CP_COMMIT(); }

    for (int c = 0; c < NCH; c++) {
        CP_WAIT2();
        __syncthreads();
        const float* As = sA + (c & 3) * A_SZ;
        const float* Bs = sB + (c & 3) * B_SZ;
#pragma unroll
        for (int ks = 0; ks < 2; ks++) {
            uint32_t af[2][4];
#pragma unroll
            for (int ma = 0; ma < 2; ma++) {
                int row = wm * 32 + ma * 16 + g4;
                int base = row * A_STRIDE + ks * 8 + l4;
                af[ma][0] = f2tf(As[base]);
                af[ma][1] = f2tf(As[base + 8 * A_STRIDE]);
                af[ma][2] = f2tf(As[base + 4]);
                af[ma][3] = f2tf(As[base + 8 * A_STRIDE + 4]);
            }
            uint32_t bf[8][2];
#pragma unroll
            for (int na = 0; na < 8; na++) {
                int col = wn * 64 + na * 8;
                int bb = (ks * 8 + l4) * B_STRIDE + col + g4;
                bf[na][0] = f2tf(Bs[bb]);
                bf[na][1] = f2tf(Bs[bb + 4 * B_STRIDE]);
            }
#pragma unroll
            for (int ma = 0; ma < 2; ma++)
#pragma unroll
                for (int na = 0; na < 8; na++)
                    mma8(acc[ma][na], af[ma], bf[na]);
        }
        int nf = c + NS - 1;
        if (nf < NCH) FILL_DN(nf & 3, nf);
        CP_COMMIT();
    }
    CP_WAIT0();

    float* C = (seg < E) ? (g_pout + (size_t)seg * NTOK * H) : out;
#pragma unroll
    for (int ma = 0; ma < 2; ma++) {
        int r0 = m0 + wm * 32 + ma * 16 + g4;
#pragma unroll
        for (int na = 0; na < 8; na++) {
            int col = n0 + wn * 64 + na * 8 + l4 * 2;
            float* a = acc[ma][na];
            if (r0 < M) {
                float2 v = { a[0], a[1] };
                *(float2*)(C + (size_t)r0 * H + col) = v;
            }
            if (r0 + 8 < M) {
                float2 v = { a[2], a[3] };
                *(float2*)(C + (size_t)(r0 + 8) * H + col) = v;
            }
        }
    }
#undef FILL_DN
}

// ---------------- launch ----------------------------------------------------------
extern "C" void kernel_launch(void* const* d_in, const int* in_sizes, int n_in,
                              void* d_out, int out_size) {
    const float* x         = (const float*)d_in[0];
    const float* gate_w    = (const float*)d_in[1];
    const float* base_gu   = (const float*)d_in[2];
    const float* base_down = (const float*)d_in[3];
    const float* exp_gu    = (const float*)d_in[4];
    const float* exp_down  = (const float*)d_in[5];
    float* out = (float*)d_out;

    cudaFuncSetAttribute(k_gateup_tc, cudaFuncAttributeMaxDynamicSharedMemorySize, SMEM_BYTES);
    cudaFuncSetAttribute(k_down_tc,   cudaFuncAttributeMaxDynamicSharedMemorySize, SMEM_BYTES);

    k_zero<<<1, 32>>>();
    k_router<<<NTOK, 256>>>(x, gate_w);
    k_gateup_tc<<<dim3(II / 64, NTOK / BM, E + 1), 256, SMEM_BYTES>>>(x, base_gu, exp_gu);
    k_down_tc<<<dim3(H / 128, NTOK / BM, E + 1), 256, SMEM_BYTES>>>(base_down, exp_down, out);
    k_combine<<<dim3(H / (4 * 128), NTOK), 128>>>(out);
}

// round 5
// speedup vs baseline: 2.9867x; 1.0827x over previous
#include <cuda_runtime.h>
#include <math.h>
#include <stdint.h>

#define H    2048
#define II   4096
#define E    8
#define NTOK 2048
#define GU   (2*II)

#define BM 128
#define BK 16
#define NS 4

#define RSTR 20                       // smem row stride in floats (16 + 4 pad)
#define STG  (128 * RSTR * 4)         // 10240 bytes per stage (A or B)
#define SMEM_BYTES (2 * NS * STG)     // 81920

// ---------------- scratch ------------------------------------------------------
__device__ int   g_cnt[E];
__device__ int   g_tok[E * NTOK];
__device__ int   g_slot[NTOK * 2];
__device__ float g_w[NTOK * 2];
__device__ float g_xr[(size_t)NTOK * H];                  // tf32-rounded x
__device__ float g_mid[(size_t)(E + 1) * NTOK * II];      // rounded silu*up
__device__ float g_pout[(size_t)E * NTOK * H];
__device__ float g_wguT[(size_t)(E + 1) * GU * H];        // gate_up^T rounded [n][k]
__device__ float g_wdnT[(size_t)(E + 1) * H * II];        // down^T rounded [n][k]

// ---------------- helpers ------------------------------------------------------
__device__ __forceinline__ uint32_t smem_u32(const void* p) {
    uint32_t a;
    asm("{ .reg .u64 t; cvta.to.shared.u64 t, %1; cvt.u32.u64 %0, t; }" : "=r"(a) : "l"(p));
    return a;
}
__device__ __forceinline__ float tf32r(float f) {
    uint32_t u;
    asm("cvt.rna.tf32.f32 %0, %1;" : "=r"(u) : "f"(f));
    return __uint_as_float(u);
}
__device__ __forceinline__ void mma8(float* c, const uint32_t* a, const uint32_t* b) {
    asm volatile(
        "mma.sync.aligned.m16n8k8.row.col.f32.tf32.tf32.f32 "
        "{%0,%1,%2,%3}, {%4,%5,%6,%7}, {%8,%9}, {%0,%1,%2,%3};"
        : "+f"(c[0]), "+f"(c[1]), "+f"(c[2]), "+f"(c[3])
        : "r"(a[0]), "r"(a[1]), "r"(a[2]), "r"(a[3]), "r"(b[0]), "r"(b[1]));
}
__device__ __forceinline__ void ldsm4(uint32_t* r, uint32_t addr) {
    asm volatile("ldmatrix.sync.aligned.m8n8.x4.shared.b16 {%0,%1,%2,%3}, [%4];"
        : "=r"(r[0]), "=r"(r[1]), "=r"(r[2]), "=r"(r[3]) : "r"(addr));
}
__device__ __forceinline__ void cpa16(uint32_t dst, const void* src) {
    asm volatile("cp.async.cg.shared.global [%0], [%1], 16;" :: "r"(dst), "l"(src) : "memory");
}
#define CP_COMMIT() asm volatile("cp.async.commit_group;" ::: "memory")
#define CP_WAIT2()  asm volatile("cp.async.wait_group 2;" ::: "memory")
#define CP_WAIT0()  asm volatile("cp.async.wait_group 0;" ::: "memory")

__device__ __forceinline__ float silu(float g) { return g / (1.f + __expf(-g)); }

// ---------------- prepass kernels ------------------------------------------------
__global__ void k_round_x(const float* __restrict__ x) {
    size_t i = ((size_t)blockIdx.x * blockDim.x + threadIdx.x) * 4;
    float4 v = *(const float4*)(x + i);
    float4 w = { tf32r(v.x), tf32r(v.y), tf32r(v.z), tf32r(v.w) };
    *(float4*)(g_xr + i) = w;
}

// transpose src[R][C] (C contig) -> dst[C][R], with tf32 rounding
__global__ void k_transpose(const float* __restrict__ src, float* __restrict__ dst,
                            int R, int C, size_t sseg, size_t dseg) {
    __shared__ float tile[32][33];
    int seg = blockIdx.z;
    src += (size_t)seg * sseg;
    dst += (size_t)seg * dseg;
    int bc = blockIdx.x * 32, br = blockIdx.y * 32;
#pragma unroll
    for (int j = 0; j < 4; j++) {
        int r = br + threadIdx.y + j * 8;
        tile[threadIdx.y + j * 8][threadIdx.x] = src[(size_t)r * C + bc + threadIdx.x];
    }
    __syncthreads();
#pragma unroll
    for (int j = 0; j < 4; j++) {
        int c = bc + threadIdx.y + j * 8;
        dst[(size_t)c * R + br + threadIdx.x] = tf32r(tile[threadIdx.x][threadIdx.y + j * 8]);
    }
}

// ---------------- small kernels --------------------------------------------------
__global__ void k_zero() { if (threadIdx.x < E) g_cnt[threadIdx.x] = 0; }

__global__ void k_router(const float* __restrict__ x, const float* __restrict__ gate_w) {
    int n = blockIdx.x;
    __shared__ float red[256][E];
    const float* xr = x + (size_t)n * H;
    float acc[E];
#pragma unroll
    for (int e = 0; e < E; e++) acc[e] = 0.f;
    for (int h = threadIdx.x; h < H; h += 256) {
        float xv = xr[h];
        const float* gw = gate_w + (size_t)h * E;
#pragma unroll
        for (int e = 0; e < E; e++) acc[e] += xv * gw[e];
    }
#pragma unroll
    for (int e = 0; e < E; e++) red[threadIdx.x][e] = acc[e];
    __syncthreads();
    for (int s = 128; s > 0; s >>= 1) {
        if (threadIdx.x < s) {
#pragma unroll
            for (int e = 0; e < E; e++) red[threadIdx.x][e] += red[threadIdx.x + s][e];
        }
        __syncthreads();
    }
    if (threadIdx.x == 0) {
        float l[E];
#pragma unroll
        for (int e = 0; e < E; e++) l[e] = red[0][e];
        int i0 = 0;
        for (int e = 1; e < E; e++) if (l[e] > l[i0]) i0 = e;
        int i1 = -1;
        for (int e = 0; e < E; e++) {
            if (e == i0) continue;
            if (i1 < 0 || l[e] > l[i1]) i1 = e;
        }
        float m  = fmaxf(l[i0], l[i1]);
        float e0 = expf(l[i0] - m), e1 = expf(l[i1] - m);
        float inv = 1.f / (e0 + e1);
        int s0 = atomicAdd(&g_cnt[i0], 1);
        int s1 = atomicAdd(&g_cnt[i1], 1);
        g_tok[i0 * NTOK + s0] = n;
        g_tok[i1 * NTOK + s1] = n;
        g_slot[n * 2 + 0] = i0 * NTOK + s0;
        g_slot[n * 2 + 1] = i1 * NTOK + s1;
        g_w[n * 2 + 0] = e0 * inv;
        g_w[n * 2 + 1] = e1 * inv;
    }
}

__global__ void k_combine(float* __restrict__ out) {
    int n = blockIdx.y;
    int h4 = (blockIdx.x * blockDim.x + threadIdx.x) * 4;
    int s0 = g_slot[n * 2 + 0], s1 = g_slot[n * 2 + 1];
    float w0 = g_w[n * 2 + 0],  w1 = g_w[n * 2 + 1];
    float* op = out + (size_t)n * H + h4;
    float4 o  = *(float4*)op;
    float4 p0 = *(const float4*)(g_pout + (size_t)s0 * H + h4);
    float4 p1 = *(const float4*)(g_pout + (size_t)s1 * H + h4);
    o.x += w0 * p0.x + w1 * p1.x;
    o.y += w0 * p0.y + w1 * p1.y;
    o.z += w0 * p0.z + w1 * p1.z;
    o.w += w0 * p0.w + w1 * p1.w;
    *(float4*)op = o;
}

// =================================================================================
// GEMM1: gate_up + SiLU*mul. B-rows: 0..63 gate cols, 64..127 up cols.
// grid (II/64, NTOK/BM, E+1), 256 threads.
// =================================================================================
__global__ void __launch_bounds__(256) k_gateup_tc(const float* dummy)
{
    int seg = blockIdx.z;
    int m0 = blockIdx.y * BM;
    int n0g = blockIdx.x * 64;
    int M; const int* tokp = nullptr;
    if (seg < E) { M = g_cnt[seg]; tokp = g_tok + seg * NTOK; }
    else         { M = NTOK; }
    if (m0 >= M) return;
    const float* wT = g_wguT + (size_t)seg * GU * H;

    extern __shared__ float sm[];
    uint32_t smbA = smem_u32(sm);
    uint32_t smbB = smbA + NS * STG;

    int tid = threadIdx.x, lane = tid & 31, wid = tid >> 5;
    int wm = wid & 3, wn = wid >> 2;
    int g4 = lane >> 2, l4 = lane & 3;

    // ---- fill assignment: thread t copies 32B of row t>>1
    int frow = tid >> 1, u0 = (tid & 1) * 2;
    int amr = min(m0 + frow, M - 1);
    const float* a_src = g_xr + (size_t)((seg < E) ? tokp[amr] : amr) * H + u0 * 4;
    const float* b_src = wT + (size_t)((frow < 64) ? (n0g + frow) : (II + n0g + frow - 64)) * H + u0 * 4;
    uint32_t a_dst = smbA + (frow * RSTR + u0 * 4) * 4;
    uint32_t b_dst = smbB + (frow * RSTR + u0 * 4) * 4;

    // ---- ldmatrix lane offsets
    int lt = lane >> 3, lr = lane & 7;
    // A: tiles {rowblk, khalf} = {t&1, t>>1}
    uint32_t a_off = ((wm * 32 + ((lt & 1) << 3) + lr) * RSTR + ((lt >> 1) << 2)) * 4;
    // B: tiles {khalf, na_add} = {t&1, t>>1}
    uint32_t b_off[4];
#pragma unroll
    for (int p = 0; p < 4; p++) {
        int na_add = lt >> 1, khalf = lt & 1;
        int colb = (p < 2) ? (wn * 32 + (2 * p + na_add) * 8)
                           : (64 + wn * 32 + (2 * p - 4 + na_add) * 8);
        b_off[p] = ((colb + lr) * RSTR + (khalf << 2)) * 4;
    }

    float acc[2][8][4];
#pragma unroll
    for (int a = 0; a < 2; a++)
#pragma unroll
        for (int b = 0; b < 8; b++)
#pragma unroll
            for (int c = 0; c < 4; c++) acc[a][b][c] = 0.f;

    const int NCH = H / BK;   // 128

#define FILL(s, c) do {                                                \
    int k0 = (c) * BK;                                                 \
    uint32_t ad = a_dst + (s) * STG;                                   \
    cpa16(ad,      a_src + k0);                                        \
    cpa16(ad + 16, a_src + k0 + 4);                                    \
    uint32_t bd = b_dst + (s) * STG;                                   \
    cpa16(bd,      b_src + k0);                                        \
    cpa16(bd + 16, b_src + k0 + 4);                                    \
} while (0)

#pragma unroll
    for (int c = 0; c < NS - 1; c++) { FILL(c, c); CP_COMMIT(); }

    for (int c = 0; c < NCH; c++) {
        CP_WAIT2();
        __syncthreads();
        uint32_t sa = smbA + (c & 3) * STG;
        uint32_t sb = smbB + (c & 3) * STG;
#pragma unroll
        for (int ks = 0; ks < 2; ks++) {
            uint32_t af[2][4];
            ldsm4(af[0], sa + a_off + ks * 32);
            ldsm4(af[1], sa + a_off + 16 * RSTR * 4 + ks * 32);
#pragma unroll
            for (int p = 0; p < 4; p++) {
                uint32_t bf[4];
                ldsm4(bf, sb + b_off[p] + ks * 32);
                mma8(acc[0][2 * p],     af[0], bf);
                mma8(acc[0][2 * p + 1], af[0], bf + 2);
                mma8(acc[1][2 * p],     af[1], bf);
                mma8(acc[1][2 * p + 1], af[1], bf + 2);
            }
        }
        int nf = c + NS - 1;
        if (nf < NCH) FILL(nf & 3, nf);
        CP_COMMIT();
    }
    CP_WAIT0();
#undef FILL

    float* midseg = g_mid + (size_t)seg * NTOK * II;
#pragma unroll
    for (int ma = 0; ma < 2; ma++) {
        int r0 = m0 + wm * 32 + ma * 16 + g4;
#pragma unroll
        for (int na = 0; na < 4; na++) {
            int col = n0g + wn * 32 + na * 8 + l4 * 2;
            float* ga = acc[ma][na];
            float* ua = acc[ma][na + 4];
            if (r0 < M) {
                float2 v = { tf32r(silu(ga[0]) * ua[0]), tf32r(silu(ga[1]) * ua[1]) };
                *(float2*)(midseg + (size_t)r0 * II + col) = v;
            }
            if (r0 + 8 < M) {
                float2 v = { tf32r(silu(ga[2]) * ua[2]), tf32r(silu(ga[3]) * ua[3]) };
                *(float2*)(midseg + (size_t)(r0 + 8) * II + col) = v;
            }
        }
    }
}

// =================================================================================
// GEMM2: down projection. grid (H/128, NTOK/BM, E+1), 256 threads.
// =================================================================================
__global__ void __launch_bounds__(256) k_down_tc(float* __restrict__ out)
{
    int seg = blockIdx.z;
    int m0 = blockIdx.y * BM;
    int n0 = blockIdx.x * 128;
    int M;
    if (seg < E) M = g_cnt[seg];
    else         M = NTOK;
    if (m0 >= M) return;
    const float* wT = g_wdnT + (size_t)seg * H * II;

    extern __shared__ float sm[];
    uint32_t smbA = smem_u32(sm);
    uint32_t smbB = smbA + NS * STG;

    int tid = threadIdx.x, lane = tid & 31, wid = tid >> 5;
    int wm = wid & 3, wn = wid >> 2;
    int g4 = lane >> 2, l4 = lane & 3;

    int frow = tid >> 1, u0 = (tid & 1) * 2;
    int amr = min(m0 + frow, M - 1);
    const float* a_src = g_mid + (size_t)(seg * NTOK + amr) * II + u0 * 4;
    const float* b_src = wT + (size_t)(n0 + frow) * II + u0 * 4;
    uint32_t a_dst = smbA + (frow * RSTR + u0 * 4) * 4;
    uint32_t b_dst = smbB + (frow * RSTR + u0 * 4) * 4;

    int lt = lane >> 3, lr = lane & 7;
    uint32_t a_off = ((wm * 32 + ((lt & 1) << 3) + lr) * RSTR + ((lt >> 1) << 2)) * 4;
    uint32_t b_off[4];
#pragma unroll
    for (int p = 0; p < 4; p++) {
        int na_add = lt >> 1, khalf = lt & 1;
        int colb = wn * 64 + (2 * p + na_add) * 8;
        b_off[p] = ((colb + lr) * RSTR + (khalf << 2)) * 4;
    }

    float acc[2][8][4];
#pragma unroll
    for (int a = 0; a < 2; a++)
#pragma unroll
        for (int b = 0; b < 8; b++)
#pragma unroll
            for (int c = 0; c < 4; c++) acc[a][b][c] = 0.f;

    const int NCH = II / BK;  // 256

#define FILL(s, c) do {                                                \
    int k0 = (c) * BK;                                                 \
    uint32_t ad = a_dst + (s) * STG;                                   \
    cpa16(ad,      a_src + k0);                                        \
    cpa16(ad + 16, a_src + k0 + 4);                                    \
    uint32_t bd = b_dst + (s) * STG;                                   \
    cpa16(bd,      b_src + k0);                                        \
    cpa16(bd + 16, b_src + k0 + 4);                                    \
} while (0)

#pragma unroll
    for (int c = 0; c < NS - 1; c++) { FILL(c, c); CP_COMMIT(); }

    for (int c = 0; c < NCH; c++) {
        CP_WAIT2();
        __syncthreads();
        uint32_t sa = smbA + (c & 3) * STG;
        uint32_t sb = smbB + (c & 3) * STG;
#pragma unroll
        for (int ks = 0; ks < 2; ks++) {
            uint32_t af[2][4];
            ldsm4(af[0], sa + a_off + ks * 32);
            ldsm4(af[1], sa + a_off + 16 * RSTR * 4 + ks * 32);
#pragma unroll
            for (int p = 0; p < 4; p++) {
                uint32_t bf[4];
                ldsm4(bf, sb + b_off[p] + ks * 32);
                mma8(acc[0][2 * p],     af[0], bf);
                mma8(acc[0][2 * p + 1], af[0], bf + 2);
                mma8(acc[1][2 * p],     af[1], bf);
                mma8(acc[1][2 * p + 1], af[1], bf + 2);
            }
        }
        int nf = c + NS - 1;
        if (nf < NCH) FILL(nf & 3, nf);
        CP_COMMIT();
    }
    CP_WAIT0();
#undef FILL

    float* C = (seg < E) ? (g_pout + (size_t)seg * NTOK * H) : out;
#pragma unroll
    for (int ma = 0; ma < 2; ma++) {
        int r0 = m0 + wm * 32 + ma * 16 + g4;
#pragma unroll
        for (int na = 0; na < 8; na++) {
            int col = n0 + wn * 64 + na * 8 + l4 * 2;
            float* a = acc[ma][na];
            if (r0 < M) {
                float2 v = { a[0], a[1] };
                *(float2*)(C + (size_t)r0 * H + col) = v;
            }
            if (r0 + 8 < M) {
                float2 v = { a[2], a[3] };
                *(float2*)(C + (size_t)(r0 + 8) * H + col) = v;
            }
        }
    }
}

// ---------------- launch ----------------------------------------------------------
extern "C" void kernel_launch(void* const* d_in, const int* in_sizes, int n_in,
                              void* d_out, int out_size) {
    const float* x         = (const float*)d_in[0];
    const float* gate_w    = (const float*)d_in[1];
    const float* base_gu   = (const float*)d_in[2];
    const float* base_down = (const float*)d_in[3];
    const float* exp_gu    = (const float*)d_in[4];
    const float* exp_down  = (const float*)d_in[5];
    float* out = (float*)d_out;

    cudaFuncSetAttribute(k_gateup_tc, cudaFuncAttributeMaxDynamicSharedMemorySize, SMEM_BYTES);
    cudaFuncSetAttribute(k_down_tc,   cudaFuncAttributeMaxDynamicSharedMemorySize, SMEM_BYTES);

    float* wguT_base;  cudaGetSymbolAddress((void**)&wguT_base, g_wguT);
    float* wdnT_base;  cudaGetSymbolAddress((void**)&wdnT_base, g_wdnT);

    dim3 tb(32, 8);
    k_zero<<<1, 32>>>();
    k_router<<<NTOK, 256>>>(x, gate_w);
    k_round_x<<<(NTOK * H) / (256 * 4), 256>>>(x);
    // weight transposes + tf32 rounding (experts segs 0..7, base at seg 8)
    k_transpose<<<dim3(GU / 32, H / 32, E), tb>>>(exp_gu, wguT_base, H, GU,
                                                  (size_t)H * GU, (size_t)GU * H);
    k_transpose<<<dim3(GU / 32, H / 32, 1), tb>>>(base_gu, wguT_base + (size_t)E * GU * H,
                                                  H, GU, 0, 0);
    k_transpose<<<dim3(H / 32, II / 32, E), tb>>>(exp_down, wdnT_base, II, H,
                                                  (size_t)II * H, (size_t)H * II);
    k_transpose<<<dim3(H / 32, II / 32, 1), tb>>>(base_down, wdnT_base + (size_t)E * H * II,
                                                  II, H, 0, 0);

    k_gateup_tc<<<dim3(II / 64, NTOK / BM, E + 1), 256, SMEM_BYTES>>>(x);
    k_down_tc<<<dim3(H / 128, NTOK / BM, E + 1), 256, SMEM_BYTES>>>(out);
    k_combine<<<dim3(H / (4 * 128), NTOK), 128>>>(out);
}

// round 6
// speedup vs baseline: 3.1966x; 1.0703x over previous
#include <cuda_runtime.h>
#include <math.h>
#include <stdint.h>

#define H    2048
#define II   4096
#define E    8
#define NTOK 2048
#define GU   (2*II)

#define BM 128
#define BK 32
#define NS 3

#define STG 16384                       // bytes per operand-stage: 128 rows * 128B
#define SMEM_BYTES (2 * NS * STG)       // 98304

// ---------------- scratch ------------------------------------------------------
__device__ int   g_cnt[E];
__device__ int   g_tok[E * NTOK];
__device__ int   g_slot[NTOK * 2];
__device__ float g_w[NTOK * 2];
__device__ float g_xr[(size_t)NTOK * H];
__device__ float g_mid[(size_t)(E + 1) * NTOK * II];
__device__ float g_pout[(size_t)E * NTOK * H];
__device__ float g_wguT[(size_t)(E + 1) * GU * H];
__device__ float g_wdnT[(size_t)(E + 1) * H * II];

// ---------------- helpers ------------------------------------------------------
__device__ __forceinline__ uint32_t smem_u32(const void* p) {
    uint32_t a;
    asm("{ .reg .u64 t; cvta.to.shared.u64 t, %1; cvt.u32.u64 %0, t; }" : "=r"(a) : "l"(p));
    return a;
}
__device__ __forceinline__ float tf32r(float f) {
    uint32_t u;
    asm("cvt.rna.tf32.f32 %0, %1;" : "=r"(u) : "f"(f));
    return __uint_as_float(u);
}
__device__ __forceinline__ void mma8(float* c, const uint32_t* a, const uint32_t* b) {
    asm volatile(
        "mma.sync.aligned.m16n8k8.row.col.f32.tf32.tf32.f32 "
        "{%0,%1,%2,%3}, {%4,%5,%6,%7}, {%8,%9}, {%0,%1,%2,%3};"
        : "+f"(c[0]), "+f"(c[1]), "+f"(c[2]), "+f"(c[3])
        : "r"(a[0]), "r"(a[1]), "r"(a[2]), "r"(a[3]), "r"(b[0]), "r"(b[1]));
}
__device__ __forceinline__ void ldsm4(uint32_t* r, uint32_t addr) {
    asm volatile("ldmatrix.sync.aligned.m8n8.x4.shared.b16 {%0,%1,%2,%3}, [%4];"
        : "=r"(r[0]), "=r"(r[1]), "=r"(r[2]), "=r"(r[3]) : "r"(addr));
}
__device__ __forceinline__ void cpa16(uint32_t dst, const void* src) {
    asm volatile("cp.async.cg.shared.global [%0], [%1], 16;" :: "r"(dst), "l"(src) : "memory");
}
#define CP_COMMIT() asm volatile("cp.async.commit_group;" ::: "memory")
#define CP_WAIT1()  asm volatile("cp.async.wait_group 1;" ::: "memory")
#define CP_WAIT0()  asm volatile("cp.async.wait_group 0;" ::: "memory")

__device__ __forceinline__ float silu(float g) { return g / (1.f + __expf(-g)); }

// ---------------- prepass ------------------------------------------------------
__global__ void k_round_x(const float* __restrict__ x) {
    size_t i = ((size_t)blockIdx.x * blockDim.x + threadIdx.x) * 4;
    float4 v = *(const float4*)(x + i);
    float4 w = { tf32r(v.x), tf32r(v.y), tf32r(v.z), tf32r(v.w) };
    *(float4*)(g_xr + i) = w;
}

__global__ void k_transpose(const float* __restrict__ src, float* __restrict__ dst,
                            int R, int C, size_t sseg, size_t dseg) {
    __shared__ float tile[32][33];
    int seg = blockIdx.z;
    src += (size_t)seg * sseg;
    dst += (size_t)seg * dseg;
    int bc = blockIdx.x * 32, br = blockIdx.y * 32;
#pragma unroll
    for (int j = 0; j < 4; j++) {
        int r = br + threadIdx.y + j * 8;
        tile[threadIdx.y + j * 8][threadIdx.x] = src[(size_t)r * C + bc + threadIdx.x];
    }
    __syncthreads();
#pragma unroll
    for (int j = 0; j < 4; j++) {
        int c = bc + threadIdx.y + j * 8;
        dst[(size_t)c * R + br + threadIdx.x] = tf32r(tile[threadIdx.x][threadIdx.y + j * 8]);
    }
}

// ---------------- small kernels --------------------------------------------------
__global__ void k_zero() { if (threadIdx.x < E) g_cnt[threadIdx.x] = 0; }

__global__ void k_router(const float* __restrict__ x, const float* __restrict__ gate_w) {
    int n = blockIdx.x;
    __shared__ float red[256][E];
    const float* xr = x + (size_t)n * H;
    float acc[E];
#pragma unroll
    for (int e = 0; e < E; e++) acc[e] = 0.f;
    for (int h = threadIdx.x; h < H; h += 256) {
        float xv = xr[h];
        const float* gw = gate_w + (size_t)h * E;
#pragma unroll
        for (int e = 0; e < E; e++) acc[e] += xv * gw[e];
    }
#pragma unroll
    for (int e = 0; e < E; e++) red[threadIdx.x][e] = acc[e];
    __syncthreads();
    for (int s = 128; s > 0; s >>= 1) {
        if (threadIdx.x < s) {
#pragma unroll
            for (int e = 0; e < E; e++) red[threadIdx.x][e] += red[threadIdx.x + s][e];
        }
        __syncthreads();
    }
    if (threadIdx.x == 0) {
        float l[E];
#pragma unroll
        for (int e = 0; e < E; e++) l[e] = red[0][e];
        int i0 = 0;
        for (int e = 1; e < E; e++) if (l[e] > l[i0]) i0 = e;
        int i1 = -1;
        for (int e = 0; e < E; e++) {
            if (e == i0) continue;
            if (i1 < 0 || l[e] > l[i1]) i1 = e;
        }
        float m  = fmaxf(l[i0], l[i1]);
        float e0 = expf(l[i0] - m), e1 = expf(l[i1] - m);
        float inv = 1.f / (e0 + e1);
        int s0 = atomicAdd(&g_cnt[i0], 1);
        int s1 = atomicAdd(&g_cnt[i1], 1);
        g_tok[i0 * NTOK + s0] = n;
        g_tok[i1 * NTOK + s1] = n;
        g_slot[n * 2 + 0] = i0 * NTOK + s0;
        g_slot[n * 2 + 1] = i1 * NTOK + s1;
        g_w[n * 2 + 0] = e0 * inv;
        g_w[n * 2 + 1] = e1 * inv;
    }
}

__global__ void k_combine(float* __restrict__ out) {
    int n = blockIdx.y;
    int h4 = (blockIdx.x * blockDim.x + threadIdx.x) * 4;
    int s0 = g_slot[n * 2 + 0], s1 = g_slot[n * 2 + 1];
    float w0 = g_w[n * 2 + 0],  w1 = g_w[n * 2 + 1];
    float* op = out + (size_t)n * H + h4;
    float4 o  = *(float4*)op;
    float4 p0 = *(const float4*)(g_pout + (size_t)s0 * H + h4);
    float4 p1 = *(const float4*)(g_pout + (size_t)s1 * H + h4);
    o.x += w0 * p0.x + w1 * p1.x;
    o.y += w0 * p0.y + w1 * p1.y;
    o.z += w0 * p0.z + w1 * p1.z;
    o.w += w0 * p0.w + w1 * p1.w;
    *(float4*)op = o;
}

// =================================================================================
// GEMM1: gate_up + SiLU*mul. grid (II/64, NTOK/BM, E+1), 256 threads.
// =================================================================================
__global__ void __launch_bounds__(256, 2) k_gateup_tc(const float* dummy)
{
    int seg = blockIdx.z;
    int m0 = blockIdx.y * BM;
    int n0g = blockIdx.x * 64;
    int M; const int* tokp = nullptr;
    if (seg < E) { M = g_cnt[seg]; tokp = g_tok + seg * NTOK; }
    else         { M = NTOK; }
    if (m0 >= M) return;
    const float* wT = g_wguT + (size_t)seg * GU * H;

    extern __shared__ float sm[];
    uint32_t smbA = smem_u32(sm);
    uint32_t smbB = smbA + NS * STG;

    int tid = threadIdx.x, lane = tid & 31, wid = tid >> 5;
    int wm = wid & 3, wn = wid >> 2;
    int g4 = lane >> 2, l4 = lane & 3;

    // ---- fill: thread t handles row t>>1, 16 floats (half = t&1)
    int frow = tid >> 1, half = tid & 1;
    int r7f = frow & 7;
    int amr = min(m0 + frow, M - 1);
    const float* a_src = g_xr + (size_t)((seg < E) ? tokp[amr] : amr) * H + half * 16;
    const float* b_src = wT + (size_t)((frow < 64) ? (n0g + frow) : (II + n0g + frow - 64)) * H + half * 16;
    uint32_t a_dstrow = smbA + frow * 128;
    uint32_t b_dstrow = smbB + frow * 128;
    uint32_t dq[4];
#pragma unroll
    for (int q = 0; q < 4; q++) dq[q] = 16u * (uint32_t)((half * 4 + q) ^ r7f);

    // ---- ldmatrix lane addressing (same fragment maps as validated R4)
    int lt = lane >> 3, lr = lane & 7;
    uint32_t a_rowb = (uint32_t)(wm * 32 + ((lt & 1) << 3) + lr) * 128;
    int khA = lt >> 1, khB = lt & 1, na = lt >> 1;
    uint32_t xorA[4], xorB[4];
#pragma unroll
    for (int ks = 0; ks < 4; ks++) {
        xorA[ks] = 16u * (uint32_t)((2 * ks + khA) ^ lr);
        xorB[ks] = 16u * (uint32_t)((2 * ks + khB) ^ lr);
    }
    uint32_t b_rowb[4];
#pragma unroll
    for (int p = 0; p < 4; p++) {
        int colb = (p < 2) ? (wn * 32 + (2 * p + na) * 8)
                           : (64 + wn * 32 + (2 * p - 4 + na) * 8);
        b_rowb[p] = (uint32_t)(colb + lr) * 128;
    }

    float acc[2][8][4];
#pragma unroll
    for (int a = 0; a < 2; a++)
#pragma unroll
        for (int b = 0; b < 8; b++)
#pragma unroll
            for (int c = 0; c < 4; c++) acc[a][b][c] = 0.f;

    const int NCH = H / BK;   // 64

#define FILL(s, c) do {                                                   \
    int k0 = (c) * BK;                                                    \
    uint32_t ad = a_dstrow + (s) * STG;                                   \
    uint32_t bd = b_dstrow + (s) * STG;                                   \
    cpa16(ad + dq[0], a_src + k0);      cpa16(ad + dq[1], a_src + k0 + 4);  \
    cpa16(ad + dq[2], a_src + k0 + 8);  cpa16(ad + dq[3], a_src + k0 + 12); \
    cpa16(bd + dq[0], b_src + k0);      cpa16(bd + dq[1], b_src + k0 + 4);  \
    cpa16(bd + dq[2], b_src + k0 + 8);  cpa16(bd + dq[3], b_src + k0 + 12); \
} while (0)

    FILL(0, 0); CP_COMMIT();
    FILL(1, 1); CP_COMMIT();

    int st = 0, stf = 2;
    for (int c = 0; c < NCH; c++) {
        CP_WAIT1();
        __syncthreads();
        uint32_t sa = smbA + st * STG;
        uint32_t sb = smbB + st * STG;
#pragma unroll
        for (int ks = 0; ks < 4; ks++) {
            uint32_t af[2][4];
            ldsm4(af[0], sa + a_rowb + xorA[ks]);
            ldsm4(af[1], sa + a_rowb + 2048 + xorA[ks]);
#pragma unroll
            for (int p = 0; p < 4; p++) {
                uint32_t bf[4];
                ldsm4(bf, sb + b_rowb[p] + xorB[ks]);
                mma8(acc[0][2 * p],     af[0], bf);
                mma8(acc[0][2 * p + 1], af[0], bf + 2);
                mma8(acc[1][2 * p],     af[1], bf);
                mma8(acc[1][2 * p + 1], af[1], bf + 2);
            }
        }
        int nf = c + 2;
        if (nf < NCH) FILL(stf, nf);
        CP_COMMIT();
        st  = (st  == 2) ? 0 : st + 1;
        stf = (stf == 2) ? 0 : stf + 1;
    }
    CP_WAIT0();
#undef FILL

    float* midseg = g_mid + (size_t)seg * NTOK * II;
#pragma unroll
    for (int ma = 0; ma < 2; ma++) {
        int r0 = m0 + wm * 32 + ma * 16 + g4;
#pragma unroll
        for (int nn = 0; nn < 4; nn++) {
            int col = n0g + wn * 32 + nn * 8 + l4 * 2;
            float* ga = acc[ma][nn];
            float* ua = acc[ma][nn + 4];
            if (r0 < M) {
                float2 v = { tf32r(silu(ga[0]) * ua[0]), tf32r(silu(ga[1]) * ua[1]) };
                *(float2*)(midseg + (size_t)r0 * II + col) = v;
            }
            if (r0 + 8 < M) {
                float2 v = { tf32r(silu(ga[2]) * ua[2]), tf32r(silu(ga[3]) * ua[3]) };
                *(float2*)(midseg + (size_t)(r0 + 8) * II + col) = v;
            }
        }
    }
}

// =================================================================================
// GEMM2: down projection. grid (H/128, NTOK/BM, E+1), 256 threads.
// =================================================================================
__global__ void __launch_bounds__(256, 2) k_down_tc(float* __restrict__ out)
{
    int seg = blockIdx.z;
    int m0 = blockIdx.y * BM;
    int n0 = blockIdx.x * 128;
    int M;
    if (seg < E) M = g_cnt[seg];
    else         M = NTOK;
    if (m0 >= M) return;
    const float* wT = g_wdnT + (size_t)seg * H * II;

    extern __shared__ float sm[];
    uint32_t smbA = smem_u32(sm);
    uint32_t smbB = smbA + NS * STG;

    int tid = threadIdx.x, lane = tid & 31, wid = tid >> 5;
    int wm = wid & 3, wn = wid >> 2;
    int g4 = lane >> 2, l4 = lane & 3;

    int frow = tid >> 1, half = tid & 1;
    int r7f = frow & 7;
    int amr = min(m0 + frow, M - 1);
    const float* a_src = g_mid + (size_t)(seg * NTOK + amr) * II + half * 16;
    const float* b_src = wT + (size_t)(n0 + frow) * II + half * 16;
    uint32_t a_dstrow = smbA + frow * 128;
    uint32_t b_dstrow = smbB + frow * 128;
    uint32_t dq[4];
#pragma unroll
    for (int q = 0; q < 4; q++) dq[q] = 16u * (uint32_t)((half * 4 + q) ^ r7f);

    int lt = lane >> 3, lr = lane & 7;
    uint32_t a_rowb = (uint32_t)(wm * 32 + ((lt & 1) << 3) + lr) * 128;
    int khA = lt >> 1, khB = lt & 1, na = lt >> 1;
    uint32_t xorA[4], xorB[4];
#pragma unroll
    for (int ks = 0; ks < 4; ks++) {
        xorA[ks] = 16u * (uint32_t)((2 * ks + khA) ^ lr);
        xorB[ks] = 16u * (uint32_t)((2 * ks + khB) ^ lr);
    }
    uint32_t b_rowb[4];
#pragma unroll
    for (int p = 0; p < 4; p++) {
        int colb = wn * 64 + (2 * p + na) * 8;
        b_rowb[p] = (uint32_t)(colb + lr) * 128;
    }

    float acc[2][8][4];
#pragma unroll
    for (int a = 0; a < 2; a++)
#pragma unroll
        for (int b = 0; b < 8; b++)
#pragma unroll
            for (int c = 0; c < 4; c++) acc[a][b][c] = 0.f;

    const int NCH = II / BK;  // 128

#define FILL(s, c) do {                                                   \
    int k0 = (c) * BK;                                                    \
    uint32_t ad = a_dstrow + (s) * STG;                                   \
    uint32_t bd = b_dstrow + (s) * STG;                                   \
    cpa16(ad + dq[0], a_src + k0);      cpa16(ad + dq[1], a_src + k0 + 4);  \
    cpa16(ad + dq[2], a_src + k0 + 8);  cpa16(ad + dq[3], a_src + k0 + 12); \
    cpa16(bd + dq[0], b_src + k0);      cpa16(bd + dq[1], b_src + k0 + 4);  \
    cpa16(bd + dq[2], b_src + k0 + 8);  cpa16(bd + dq[3], b_src + k0 + 12); \
} while (0)

    FILL(0, 0); CP_COMMIT();
    FILL(1, 1); CP_COMMIT();

    int st = 0, stf = 2;
    for (int c = 0; c < NCH; c++) {
        CP_WAIT1();
        __syncthreads();
        uint32_t sa = smbA + st * STG;
        uint32_t sb = smbB + st * STG;
#pragma unroll
        for (int ks = 0; ks < 4; ks++) {
            uint32_t af[2][4];
            ldsm4(af[0], sa + a_rowb + xorA[ks]);
            ldsm4(af[1], sa + a_rowb + 2048 + xorA[ks]);
#pragma unroll
            for (int p = 0; p < 4; p++) {
                uint32_t bf[4];
                ldsm4(bf, sb + b_rowb[p] + xorB[ks]);
                mma8(acc[0][2 * p],     af[0], bf);
                mma8(acc[0][2 * p + 1], af[0], bf + 2);
                mma8(acc[1][2 * p],     af[1], bf);
                mma8(acc[1][2 * p + 1], af[1], bf + 2);
            }
        }
        int nf = c + 2;
        if (nf < NCH) FILL(stf, nf);
        CP_COMMIT();
        st  = (st  == 2) ? 0 : st + 1;
        stf = (stf == 2) ? 0 : stf + 1;
    }
    CP_WAIT0();
#undef FILL

    float* C = (seg < E) ? (g_pout + (size_t)seg * NTOK * H) : out;
#pragma unroll
    for (int ma = 0; ma < 2; ma++) {
        int r0 = m0 + wm * 32 + ma * 16 + g4;
#pragma unroll
        for (int nn = 0; nn < 8; nn++) {
            int col = n0 + wn * 64 + nn * 8 + l4 * 2;
            float* a = acc[ma][nn];
            if (r0 < M) {
                float2 v = { a[0], a[1] };
                *(float2*)(C + (size_t)r0 * H + col) = v;
            }
            if (r0 + 8 < M) {
                float2 v = { a[2], a[3] };
                *(float2*)(C + (size_t)(r0 + 8) * H + col) = v;
            }
        }
    }
}

// ---------------- launch ----------------------------------------------------------
extern "C" void kernel_launch(void* const* d_in, const int* in_sizes, int n_in,
                              void* d_out, int out_size) {
    const float* x         = (const float*)d_in[0];
    const float* gate_w    = (const float*)d_in[1];
    const float* base_gu   = (const float*)d_in[2];
    const float* base_down = (const float*)d_in[3];
    const float* exp_gu    = (const float*)d_in[4];
    const float* exp_down  = (const float*)d_in[5];
    float* out = (float*)d_out;

    cudaFuncSetAttribute(k_gateup_tc, cudaFuncAttributeMaxDynamicSharedMemorySize, SMEM_BYTES);
    cudaFuncSetAttribute(k_down_tc,   cudaFuncAttributeMaxDynamicSharedMemorySize, SMEM_BYTES);

    float* wguT_base;  cudaGetSymbolAddress((void**)&wguT_base, g_wguT);
    float* wdnT_base;  cudaGetSymbolAddress((void**)&wdnT_base, g_wdnT);

    dim3 tb(32, 8);
    k_zero<<<1, 32>>>();
    k_router<<<NTOK, 256>>>(x, gate_w);
    k_round_x<<<(NTOK * H) / (256 * 4), 256>>>(x);
    k_transpose<<<dim3(GU / 32, H / 32, E), tb>>>(exp_gu, wguT_base, H, GU,
                                                  (size_t)H * GU, (size_t)GU * H);
    k_transpose<<<dim3(GU / 32, H / 32, 1), tb>>>(base_gu, wguT_base + (size_t)E * GU * H,
                                                  H, GU, 0, 0);
    k_transpose<<<dim3(H / 32, II / 32, E), tb>>>(exp_down, wdnT_base, II, H,
                                                  (size_t)II * H, (size_t)H * II);
    k_transpose<<<dim3(H / 32, II / 32, 1), tb>>>(base_down, wdnT_base + (size_t)E * H * II,
                                                  II, H, 0, 0);

    k_gateup_tc<<<dim3(II / 64, NTOK / BM, E + 1), 256, SMEM_BYTES>>>(x);
    k_down_tc<<<dim3(H / 128, NTOK / BM, E + 1), 256, SMEM_BYTES>>>(out);
    k_combine<<<dim3(H / (4 * 128), NTOK), 128>>>(out);
}